// round 13
// baseline (speedup 1.0000x reference)
#include <cuda_runtime.h>
#include <cuda_bf16.h>
#include <math.h>
#include <stdint.h>

// Problem constants
#define BATCH 32
#define TT 64
#define SS 64
#define VV 32000
#define EE 512
#define HH 512
#define NCTA 128

// ---------------- device scratch ----------------
__device__ float g_embF[2048 * 512];             // embedded fp32, row = t*32+b
__device__ float g_encproj[2048 * 512];          // enc @ W_a, row = b*64+s
__device__ float g_encIHC[2048 * 2048];          // enc @ Wih0[:,512:]^T
__device__ float g_h[2 * BATCH * HH];            // fp32 state [h0 | h1]
__device__ float g_c[2 * BATCH * HH];
__device__ float g_feat[TT * BATCH * 1024];      // [t][b][ h1 | ctx ]
__device__ float g_embpre[TT * BATCH * 2048];    // emb @ Wih0[:, :512]^T
__device__ float g_g0hh[BATCH * 2048];
__device__ float g_g1hh[BATCH * 2048];
__device__ float g_g1ih[BATCH * 2048];
__device__ float g_attw[BATCH * 64];             // normalized attention weights
__device__ unsigned g_barcnt;
// bf16 split operands for big projection GEMM
__device__ __nv_bfloat16 g_WH[VV * 1024];
__device__ __nv_bfloat16 g_WL[VV * 1024];
__device__ __nv_bfloat16 g_fH[2048 * 1024];
__device__ __nv_bfloat16 g_fL[2048 * 1024];

// ---------------- PTX helpers ----------------
__device__ __forceinline__ uint32_t smem_to_u32(const void* p) {
    uint32_t a;
    asm("{ .reg .u64 t; cvta.to.shared.u64 t, %1; cvt.u32.u64 %0, t; }" : "=r"(a) : "l"(p));
    return a;
}
#define CP16(dst, src) \
    asm volatile("cp.async.cg.shared.global [%0], [%1], 16;" \
                 :: "r"(dst), "l"(src) : "memory")
#define CP_COMMIT() asm volatile("cp.async.commit_group;" ::: "memory")
#define CP_WAIT0()  asm volatile("cp.async.wait_group 0;" ::: "memory")
#define CP_WAIT1()  asm volatile("cp.async.wait_group 1;" ::: "memory")

#define LDSM_X4(r0, r1, r2, r3, addr) \
    asm volatile("ldmatrix.sync.aligned.m8n8.x4.shared.b16 {%0,%1,%2,%3}, [%4];" \
                 : "=r"(r0), "=r"(r1), "=r"(r2), "=r"(r3) : "r"(addr))
#define LDSM_X2(r0, r1, addr) \
    asm volatile("ldmatrix.sync.aligned.m8n8.x2.shared.b16 {%0,%1}, [%2];" \
                 : "=r"(r0), "=r"(r1) : "r"(addr))

#define MMA_BF16(c, a0, a1, a2, a3, b0, b1) \
    asm volatile("mma.sync.aligned.m16n8k16.row.col.f32.bf16.bf16.f32 " \
                 "{%0,%1,%2,%3}, {%4,%5,%6,%7}, {%8,%9}, {%0,%1,%2,%3};" \
                 : "+f"((c)[0]), "+f"((c)[1]), "+f"((c)[2]), "+f"((c)[3]) \
                 : "r"(a0), "r"(a1), "r"(a2), "r"(a3), "r"(b0), "r"(b1))

__device__ __forceinline__ unsigned short bf16hi(float x) {
    return __bfloat16_as_ushort(__float2bfloat16(x));
}
__device__ __forceinline__ void split4(float4 x, uint2& hv, uint2& lv) {
    unsigned short h0 = bf16hi(x.x), h1 = bf16hi(x.y), h2 = bf16hi(x.z), h3 = bf16hi(x.w);
    unsigned short l0 = bf16hi(x.x - __bfloat162float(__ushort_as_bfloat16(h0)));
    unsigned short l1 = bf16hi(x.y - __bfloat162float(__ushort_as_bfloat16(h1)));
    unsigned short l2 = bf16hi(x.z - __bfloat162float(__ushort_as_bfloat16(h2)));
    unsigned short l3 = bf16hi(x.w - __bfloat162float(__ushort_as_bfloat16(h3)));
    hv.x = (uint32_t)h0 | ((uint32_t)h1 << 16);
    hv.y = (uint32_t)h2 | ((uint32_t)h3 << 16);
    lv.x = (uint32_t)l0 | ((uint32_t)l1 << 16);
    lv.y = (uint32_t)l2 | ((uint32_t)l3 << 16);
}

// ---------------- utility kernels ----------------
__global__ void init_state_kernel(const float* __restrict__ hidden,
                                  const float* __restrict__ cell) {
    int i = blockIdx.x * blockDim.x + threadIdx.x;
    if (i == 0) g_barcnt = 0u;
    if (i < 2 * BATCH * HH) { g_h[i] = hidden[i]; g_c[i] = cell[i]; }
}

__global__ void tail_copy_kernel(float* __restrict__ out) {
    int i = blockIdx.x * blockDim.x + threadIdx.x;
    const long long OFF = (long long)BATCH * TT * VV;
    if (i < 2 * BATCH * HH) {
        out[OFF + i] = g_h[i];
        out[OFF + 2 * BATCH * HH + i] = g_c[i];
    }
}

__global__ void embed_kernel(const int* __restrict__ tgt,
                             const float* __restrict__ emb) {
    int blk = blockIdx.x;             // b*TT + t
    int b = blk >> 6, t = blk & 63;
    int idx = tgt[blk];
    int e = threadIdx.x * 4;
    float4 v;
    if (idx == 0) { v.x = v.y = v.z = v.w = 0.f; }
    else v = *reinterpret_cast<const float4*>(emb + (long long)idx * EE + e);
    *reinterpret_cast<float4*>(g_embF + (long long)(t * 32 + b) * 512 + e) = v;
}

// ---------------- fp32 prep GEMM (NT): C = A[:,512] @ B^T -------------------
__global__ __launch_bounds__(256)
void gemm64_nt_f32(const float* __restrict__ A,
                   const float* __restrict__ B, int ldb,
                   float* __restrict__ C, int ldc) {
    __shared__ __align__(16) float As[16][68];
    __shared__ __align__(16) float Bs[16][68];
    const int tid = threadIdx.x;
    const int m0 = blockIdx.y * 64, n0 = blockIdx.x * 64;
    const int lr = tid >> 2, lc = (tid & 3) * 4;
    const int tm = (tid >> 4) * 4, tn = (tid & 15) * 4;
    float acc[4][4] = {};
    for (int k0 = 0; k0 < 512; k0 += 16) {
        float4 av = *reinterpret_cast<const float4*>(A + (long long)(m0 + lr) * 512 + k0 + lc);
        As[lc + 0][lr] = av.x; As[lc + 1][lr] = av.y; As[lc + 2][lr] = av.z; As[lc + 3][lr] = av.w;
        float4 wv = *reinterpret_cast<const float4*>(B + (long long)(n0 + lr) * ldb + k0 + lc);
        Bs[lc + 0][lr] = wv.x; Bs[lc + 1][lr] = wv.y; Bs[lc + 2][lr] = wv.z; Bs[lc + 3][lr] = wv.w;
        __syncthreads();
        #pragma unroll
        for (int kk = 0; kk < 16; kk++) {
            float4 a = *reinterpret_cast<const float4*>(&As[kk][tm]);
            float4 b = *reinterpret_cast<const float4*>(&Bs[kk][tn]);
            acc[0][0] += a.x * b.x; acc[0][1] += a.x * b.y; acc[0][2] += a.x * b.z; acc[0][3] += a.x * b.w;
            acc[1][0] += a.y * b.x; acc[1][1] += a.y * b.y; acc[1][2] += a.y * b.z; acc[1][3] += a.y * b.w;
            acc[2][0] += a.z * b.x; acc[2][1] += a.z * b.y; acc[2][2] += a.z * b.z; acc[2][3] += a.z * b.w;
            acc[3][0] += a.w * b.x; acc[3][1] += a.w * b.y; acc[3][2] += a.w * b.z; acc[3][3] += a.w * b.w;
        }
        __syncthreads();
    }
    #pragma unroll
    for (int i = 0; i < 4; i++) {
        float4 o = make_float4(acc[i][0], acc[i][1], acc[i][2], acc[i][3]);
        *reinterpret_cast<float4*>(C + (long long)(m0 + tm + i) * ldc + n0 + tn) = o;
    }
}

// ---------------- fp32 prep GEMM (NN): C = A[:,512] @ B ---------------------
__global__ __launch_bounds__(256)
void gemm64_nn_f32(const float* __restrict__ A,
                   const float* __restrict__ B, int ldb,
                   float* __restrict__ C, int ldc) {
    __shared__ __align__(16) float As[16][68];
    __shared__ __align__(16) float Bs[16][68];
    const int tid = threadIdx.x;
    const int m0 = blockIdx.y * 64, n0 = blockIdx.x * 64;
    const int lr = tid >> 2, lc = (tid & 3) * 4;
    const int kr = tid >> 4, jc = (tid & 15) * 4;
    const int tm = (tid >> 4) * 4, tn = (tid & 15) * 4;
    float acc[4][4] = {};
    for (int k0 = 0; k0 < 512; k0 += 16) {
        float4 av = *reinterpret_cast<const float4*>(A + (long long)(m0 + lr) * 512 + k0 + lc);
        As[lc + 0][lr] = av.x; As[lc + 1][lr] = av.y; As[lc + 2][lr] = av.z; As[lc + 3][lr] = av.w;
        float4 bv = *reinterpret_cast<const float4*>(B + (long long)(k0 + kr) * ldb + n0 + jc);
        *reinterpret_cast<float4*>(&Bs[kr][jc]) = bv;
        __syncthreads();
        #pragma unroll
        for (int kk = 0; kk < 16; kk++) {
            float4 a = *reinterpret_cast<const float4*>(&As[kk][tm]);
            float4 b = *reinterpret_cast<const float4*>(&Bs[kk][tn]);
            acc[0][0] += a.x * b.x; acc[0][1] += a.x * b.y; acc[0][2] += a.x * b.z; acc[0][3] += a.x * b.w;
            acc[1][0] += a.y * b.x; acc[1][1] += a.y * b.y; acc[1][2] += a.y * b.z; acc[1][3] += a.y * b.w;
            acc[2][0] += a.z * b.x; acc[2][1] += a.z * b.y; acc[2][2] += a.z * b.z; acc[2][3] += a.z * b.w;
            acc[3][0] += a.w * b.x; acc[3][1] += a.w * b.y; acc[3][2] += a.w * b.z; acc[3][3] += a.w * b.w;
        }
        __syncthreads();
    }
    #pragma unroll
    for (int i = 0; i < 4; i++) {
        float4 o = make_float4(acc[i][0], acc[i][1], acc[i][2], acc[i][3]);
        *reinterpret_cast<float4*>(C + (long long)(m0 + tm + i) * ldc + n0 + tn) = o;
    }
}

// ---------------- persistent recurrence --------------------------------------
// smem: sW1[32*512] | sW2[32*512] | sA[512*33] ; overlays live in sA region.
#define SW_FLOATS (32 * 512)
#define SA_FLOATS (512 * 33)
#define DSM_BYTES ((2 * SW_FLOATS + SA_FLOATS) * 4)

__device__ __forceinline__ float sigmf(float x) { return 1.f / (1.f + expf(-x)); }

// load W rows [n0, n0+32) x 512 into smem tile (col*512+k layout)
__device__ __forceinline__ void loadW(const float* __restrict__ W, int n0,
                                      float* sW, int tid) {
    const float* Wr = W + (long long)n0 * 512;
    for (int i = tid; i < 32 * 128; i += 256) {
        int col = i >> 7, kq = (i & 127) << 2;
        float4 v = __ldg(reinterpret_cast<const float4*>(Wr + (long long)col * 512 + kq));
        *reinterpret_cast<float4*>(sW + col * 512 + kq) = v;
    }
}

// C[32 rows, 32 cols @ n0] = A[32x512] @ sW^T  (W resident in smem)
__device__ __forceinline__ void fgemm_tile32_pre(
    const float* __restrict__ A, const float* sW, int n0,
    float* __restrict__ C, int ldc, float* sA, int tid)
{
    for (int i = tid; i < 32 * 128; i += 256) {
        int b = i >> 7, kq = (i & 127) << 2;
        float4 v = __ldcg(reinterpret_cast<const float4*>(A + b * 512 + kq));
        sA[(kq + 0) * 33 + b] = v.x;
        sA[(kq + 1) * 33 + b] = v.y;
        sA[(kq + 2) * 33 + b] = v.z;
        sA[(kq + 3) * 33 + b] = v.w;
    }
    __syncthreads();
    const int b = tid & 31, cg = tid >> 5;
    float a0c = 0.f, a1c = 0.f, a2c = 0.f, a3c = 0.f;
    const float* bp = sW + cg * 4 * 512;
    #pragma unroll 4
    for (int k = 0; k < 512; k += 4) {
        float a0 = sA[(k + 0) * 33 + b];
        float a1 = sA[(k + 1) * 33 + b];
        float a2 = sA[(k + 2) * 33 + b];
        float a3 = sA[(k + 3) * 33 + b];
        float4 b0 = *reinterpret_cast<const float4*>(bp + k);
        float4 b1 = *reinterpret_cast<const float4*>(bp + 512 + k);
        float4 b2 = *reinterpret_cast<const float4*>(bp + 1024 + k);
        float4 b3 = *reinterpret_cast<const float4*>(bp + 1536 + k);
        a0c += a0 * b0.x; a0c += a1 * b0.y; a0c += a2 * b0.z; a0c += a3 * b0.w;
        a1c += a0 * b1.x; a1c += a1 * b1.y; a1c += a2 * b1.z; a1c += a3 * b1.w;
        a2c += a0 * b2.x; a2c += a1 * b2.y; a2c += a2 * b2.z; a2c += a3 * b2.w;
        a3c += a0 * b3.x; a3c += a1 * b3.y; a3c += a2 * b3.z; a3c += a3 * b3.w;
    }
    __stcg(reinterpret_cast<float4*>(C + (long long)b * ldc + n0 + cg * 4),
           make_float4(a0c, a1c, a2c, a3c));
    __syncthreads();
}

__global__ __launch_bounds__(256, 1)
void decoder_persistent(const float* __restrict__ enc,
                        const float* __restrict__ W_hh0,
                        const float* __restrict__ W_hh1,
                        const float* __restrict__ W_ih1,
                        const float* __restrict__ b_ih0,
                        const float* __restrict__ b_hh0,
                        const float* __restrict__ b_ih1,
                        const float* __restrict__ b_hh1,
                        const float4* __restrict__ Wout4) {
    extern __shared__ float dsm[];
    float* sW1 = dsm;
    float* sW2 = dsm + SW_FLOATS;
    float* sA  = dsm + 2 * SW_FLOATS;
    // overlays (in sA region)
    float* h1s = sA;                 // attn: 512
    float* sc = sA + 512;            // attn: 64
    float* sred = sA + 580;          // attn: 2
    float* attw_sm = sA;             // phase C: 64
    float* sg = sA + 64;             // phase C: 4*128

    const int cta = blockIdx.x;
    const int tid = threadIdx.x;
    const int lane = tid & 31;
    const int wid = tid >> 5;
    unsigned bar_t = 0;
    unsigned* barp = &g_barcnt;

    auto gbar = [&]() {
        __syncthreads();
        bar_t += NCTA;
        if (tid == 0) {
            asm volatile("red.release.gpu.global.add.u32 [%0], 1;"
                         :: "l"(barp) : "memory");
            unsigned v;
            do {
                asm volatile("ld.acquire.gpu.global.u32 %0, [%1];"
                             : "=r"(v) : "l"(barp) : "memory");
            } while (v < bar_t);
        }
        __syncthreads();
    };

    float* h0 = g_h;
    float* h1 = g_h + 16384;

    // ---- preload resident weight tiles ----
    if (cta < 64)      { loadW(W_hh0, cta * 32, sW1, tid); loadW(W_ih1, cta * 32, sW2, tid); }
    else if (cta < 96) { loadW(W_hh1, (cta - 32) * 32, sW1, tid); }
    else               { loadW(W_hh1, (cta - 96) * 32, sW1, tid); }
    __syncthreads();

    // phase-C constants for this CTA
    const int cb = cta >> 2;             // batch for LSTM phases
    const int u0 = (cta & 3) * 128;

    for (int t = 0; t < TT; t++) {
        float* feat_t = g_feat + t * 32768;
        const float* ep = g_embpre + (long long)t * 65536;

        // ==== Phase A: g0hh (0-63) | attn (64-95) | g1hh tiles 0-31 (96-127)
        if (cta < 64) {
            fgemm_tile32_pre(h0, sW1, cta * 32, g_g0hh, 2048, sA, tid);
        } else if (cta < 96) {
            const int b = cta - 64;
            #pragma unroll
            for (int r = 0; r < 2; r++) {
                int k = tid + r * 256;
                h1s[k] = __ldcg(h1 + b * 512 + k);
            }
            __syncthreads();
            const float* epj = g_encproj + (long long)b * 64 * 512;
            #pragma unroll
            for (int si = 0; si < 8; si++) {
                int s = wid * 8 + si;
                const float* row = epj + s * 512;
                float sum = 0.f;
                for (int j = lane; j < 512; j += 32) sum += row[j] * h1s[j];
                #pragma unroll
                for (int o = 16; o; o >>= 1) sum += __shfl_down_sync(0xffffffffu, sum, o);
                if (lane == 0) sc[s] = sum;
            }
            __syncthreads();
            if (tid == 0) {
                float mx = sc[0];
                for (int s = 1; s < 64; s++) mx = fmaxf(mx, sc[s]);
                sred[0] = mx;
            }
            __syncthreads();
            if (tid < 64) sc[tid] = expf(sc[tid] - sred[0]);
            __syncthreads();
            if (tid == 0) {
                float sm = 0.f;
                for (int s = 0; s < 64; s++) sm += sc[s];
                sred[1] = 1.f / sm;
            }
            __syncthreads();
            const float inv = sred[1];
            // publish normalized weights
            if (tid < 64) __stcg(g_attw + b * 64 + tid, sc[tid] * inv);
            // ctx: 2 cols/thread
            {
                const float* encb = enc + (long long)b * SS * 512 + tid * 2;
                float c0 = 0.f, c1 = 0.f;
                #pragma unroll 8
                for (int s = 0; s < 64; s++) {
                    float w = sc[s];
                    float2 x = *reinterpret_cast<const float2*>(encb + s * 512);
                    c0 += w * x.x; c1 += w * x.y;
                }
                feat_t[b * 1024 + 512 + tid * 2]     = c0 * inv;
                feat_t[b * 1024 + 512 + tid * 2 + 1] = c1 * inv;
            }
            __syncthreads();
        } else {
            fgemm_tile32_pre(h1, sW1, (cta - 96) * 32, g_g1hh, 2048, sA, tid);
        }
        gbar();

        // ==== Phase C: g0ctx slice + LSTM0 (all 128 CTAs) ====
        {
            if (tid < 64) attw_sm[tid] = __ldcg(g_attw + cb * 64 + tid);
            __syncthreads();
            const int half = tid >> 7, i = tid & 127, u = u0 + i;
            #pragma unroll
            for (int g2 = 0; g2 < 2; g2++) {
                int q = half * 2 + g2;
                const float* base = g_encIHC + (long long)(cb * 64) * 2048 + q * 512 + u;
                float acc = 0.f;
                #pragma unroll 8
                for (int s = 0; s < 64; s++)
                    acc += attw_sm[s] * __ldcg(base + (long long)s * 2048);
                sg[q * 128 + i] = acc;
            }
            // feat split (slice t-1) while dots are in flight
            if (t > 0 && tid < 64) {
                int i4 = (t - 1) * 8192 + cta * 64 + tid;
                float4 x = __ldcg(reinterpret_cast<const float4*>(g_feat) + i4);
                uint2 hv, lv;
                split4(x, hv, lv);
                reinterpret_cast<uint2*>(g_fH)[i4] = hv;
                reinterpret_cast<uint2*>(g_fL)[i4] = lv;
            }
            __syncthreads();
            if (tid < 128) {
                int u2 = u0 + tid;
                int idx = cb * 512 + u2;
                float gv[4];
                #pragma unroll
                for (int q = 0; q < 4; q++) {
                    int o = cb * 2048 + q * 512 + u2;
                    gv[q] = ep[o] + __ldcg(g_g0hh + o) + sg[q * 128 + tid]
                          + __ldg(b_ih0 + q * 512 + u2) + __ldg(b_hh0 + q * 512 + u2);
                }
                float cv = g_c[idx];
                float cn = sigmf(gv[1]) * cv + sigmf(gv[0]) * tanhf(gv[2]);
                float hn = sigmf(gv[3]) * tanhf(cn);
                g_c[idx] = cn;
                __stcg(h0 + idx, hn);
            }
            __syncthreads();
        }
        gbar();

        // ==== Phase D: g1ih (0-63) | g1hh tiles 32-63 (64-95) ====
        if (cta < 64) {
            fgemm_tile32_pre(h0, sW2, cta * 32, g_g1ih, 2048, sA, tid);
        } else if (cta < 96) {
            fgemm_tile32_pre(h1, sW1, (cta - 32) * 32, g_g1hh, 2048, sA, tid);
        }
        gbar();

        // ==== Phase E: LSTM1 + feat write + W_out split chunk ====
        {
            if (tid < 128) {
                int u2 = u0 + tid;
                int idx = cb * 512 + u2;
                float gv[4];
                #pragma unroll
                for (int q = 0; q < 4; q++) {
                    int o = cb * 2048 + q * 512 + u2;
                    gv[q] = __ldcg(g_g1hh + o) + __ldcg(g_g1ih + o)
                          + __ldg(b_ih1 + q * 512 + u2) + __ldg(b_hh1 + q * 512 + u2);
                }
                float cv = g_c[16384 + idx];
                float cn = sigmf(gv[1]) * cv + sigmf(gv[0]) * tanhf(gv[2]);
                float hn = sigmf(gv[3]) * tanhf(cn);
                g_c[16384 + idx] = cn;
                __stcg(h1 + idx, hn);
                feat_t[cb * 1024 + u2] = hn;
            }
            // W_out split chunk: 128K float4 per step
            long long base4 = (long long)t * 131072 + cta * 1024 + tid;
            #pragma unroll
            for (int k = 0; k < 4; k++) {
                long long i4 = base4 + k * 256;
                if (i4 < (long long)VV * 256) {
                    float4 x = __ldg(Wout4 + i4);
                    uint2 hv, lv;
                    split4(x, hv, lv);
                    reinterpret_cast<uint2*>(g_WH)[i4] = hv;
                    reinterpret_cast<uint2*>(g_WL)[i4] = lv;
                }
            }
        }
        gbar();
    }

    // final feat slice (t = 63) split
    if (tid < 64) {
        int i4 = 63 * 8192 + cta * 64 + tid;
        float4 x = __ldcg(reinterpret_cast<const float4*>(g_feat) + i4);
        uint2 hv, lv;
        split4(x, hv, lv);
        reinterpret_cast<uint2*>(g_fH)[i4] = hv;
        reinterpret_cast<uint2*>(g_fL)[i4] = lv;
    }
}

// ---------------- big projection GEMM (3-term bf16, unchanged) ----------------
#define GK 1024
#define KC 32
#define NKC (GK / KC)
#define RST 40
#define BUF_BF16 (128 * RST)
#define STAGE_BF16 (4 * BUF_BF16)
#define GEMM_SMEM (2 * STAGE_BF16 * 2)

__global__ __launch_bounds__(256, 1)
void big_gemm_mma(const __nv_bfloat16* __restrict__ AH, const __nv_bfloat16* __restrict__ AL,
                  const __nv_bfloat16* __restrict__ BH, const __nv_bfloat16* __restrict__ BL,
                  const float* __restrict__ bias, float* __restrict__ out) {
    extern __shared__ __nv_bfloat16 sm[];
    const int tid = threadIdx.x;
    const int lane = tid & 31;
    const int wid = tid >> 5;
    const int wm = wid >> 1;
    const int wn = wid & 1;
    const int m0 = blockIdx.x * 128;
    const int n0 = blockIdx.y * 128;
    const uint32_t smem_base = smem_to_u32(sm);

    float acc[2][8][4];
    #pragma unroll
    for (int i = 0; i < 2; i++)
        #pragma unroll
        for (int j = 0; j < 8; j++)
            #pragma unroll
            for (int v = 0; v < 4; v++) acc[i][j][v] = 0.f;

    auto load_stage = [&](int st, int kc) {
        const uint32_t sb = smem_base + st * STAGE_BF16 * 2;
        const int k0 = kc * KC;
        #pragma unroll
        for (int r = 0; r < 2; r++) {
            int idx = tid + r * 256;
            int row = idx >> 2, c = idx & 3;
            uint32_t doff = (uint32_t)(row * RST + c * 8) * 2;
            long long aoff = (long long)(m0 + row) * GK + k0 + c * 8;
            long long boff = (long long)(n0 + row) * GK + k0 + c * 8;
            CP16(sb + doff,                AH + aoff);
            CP16(sb + BUF_BF16 * 2 + doff, AL + aoff);
            CP16(sb + BUF_BF16 * 4 + doff, BH + boff);
            CP16(sb + BUF_BF16 * 6 + doff, BL + boff);
        }
        CP_COMMIT();
    };

    load_stage(0, 0);

    for (int kc = 0; kc < NKC; kc++) {
        const int st = kc & 1;
        if (kc + 1 < NKC) { load_stage(st ^ 1, kc + 1); CP_WAIT1(); }
        else              { CP_WAIT0(); }
        __syncthreads();

        const uint32_t sb = smem_base + st * STAGE_BF16 * 2;
        uint32_t ah[2][2][4], al[2][2][4];
        #pragma unroll
        for (int i = 0; i < 2; i++)
            #pragma unroll
            for (int kk = 0; kk < 2; kk++) {
                uint32_t addr = sb + (uint32_t)((wm * 32 + i * 16 + (lane & 15)) * RST
                                                + kk * 16 + (lane >> 4) * 8) * 2;
                LDSM_X4(ah[i][kk][0], ah[i][kk][1], ah[i][kk][2], ah[i][kk][3], addr);
                LDSM_X4(al[i][kk][0], al[i][kk][1], al[i][kk][2], al[i][kk][3],
                        addr + BUF_BF16 * 2);
            }
        #pragma unroll
        for (int j = 0; j < 8; j++) {
            #pragma unroll
            for (int kk = 0; kk < 2; kk++) {
                uint32_t baddr = sb + BUF_BF16 * 4
                    + (uint32_t)((wn * 64 + j * 8 + (lane & 7)) * RST
                                 + kk * 16 + ((lane >> 3) & 1) * 8) * 2;
                uint32_t bh0, bh1, bl0, bl1;
                LDSM_X2(bh0, bh1, baddr);
                LDSM_X2(bl0, bl1, baddr + BUF_BF16 * 2);
                #pragma unroll
                for (int i = 0; i < 2; i++) {
                    MMA_BF16(acc[i][j], ah[i][kk][0], ah[i][kk][1], ah[i][kk][2], ah[i][kk][3], bh0, bh1);
                    MMA_BF16(acc[i][j], al[i][kk][0], al[i][kk][1], al[i][kk][2], al[i][kk][3], bh0, bh1);
                    MMA_BF16(acc[i][j], ah[i][kk][0], ah[i][kk][1], ah[i][kk][2], ah[i][kk][3], bl0, bl1);
                }
            }
        }
        __syncthreads();
    }

    #pragma unroll
    for (int i = 0; i < 2; i++) {
        int mA = m0 + wm * 32 + i * 16 + (lane >> 2);
        int mB = mA + 8;
        int tA = mA >> 5, bA = mA & 31;
        int tB = mB >> 5, bB = mB & 31;
        float* rowA = out + (long long)((bA << 6) + tA) * VV;
        float* rowB = out + (long long)((bB << 6) + tB) * VV;
        #pragma unroll
        for (int j = 0; j < 8; j++) {
            int n = n0 + wn * 64 + j * 8 + (lane & 3) * 2;
            float bv0 = bias[n], bv1 = bias[n + 1];
            float2 vA = make_float2(acc[i][j][0] + bv0, acc[i][j][1] + bv1);
            float2 vB = make_float2(acc[i][j][2] + bv0, acc[i][j][3] + bv1);
            *reinterpret_cast<float2*>(rowA + n) = vA;
            *reinterpret_cast<float2*>(rowB + n) = vB;
        }
    }
}

// ---------------- host launcher ----------------
extern "C" void kernel_launch(void* const* d_in, const int* in_sizes, int n_in,
                              void* d_out, int out_size) {
    const int*   tgt    = (const int*)  d_in[0];
    const float* enc    = (const float*)d_in[1];
    const float* hidden = (const float*)d_in[2];
    const float* cell   = (const float*)d_in[3];
    const float* emb    = (const float*)d_in[4];
    const float* W_a    = (const float*)d_in[5];
    const float* W_ih0  = (const float*)d_in[6];
    const float* W_hh0  = (const float*)d_in[7];
    const float* b_ih0  = (const float*)d_in[8];
    const float* b_hh0  = (const float*)d_in[9];
    const float* W_ih1  = (const float*)d_in[10];
    const float* W_hh1  = (const float*)d_in[11];
    const float* b_ih1  = (const float*)d_in[12];
    const float* b_hh1  = (const float*)d_in[13];
    const float* W_out  = (const float*)d_in[14];
    const float* b_out  = (const float*)d_in[15];
    float* out = (float*)d_out;

    float *p_embF, *p_encproj, *p_encIHC, *p_embpre;
    __nv_bfloat16 *p_WH, *p_WL, *p_fH, *p_fL;
    cudaGetSymbolAddress((void**)&p_embF,    g_embF);
    cudaGetSymbolAddress((void**)&p_encproj, g_encproj);
    cudaGetSymbolAddress((void**)&p_encIHC,  g_encIHC);
    cudaGetSymbolAddress((void**)&p_embpre,  g_embpre);
    cudaGetSymbolAddress((void**)&p_WH,      g_WH);
    cudaGetSymbolAddress((void**)&p_WL,      g_WL);
    cudaGetSymbolAddress((void**)&p_fH,      g_fH);
    cudaGetSymbolAddress((void**)&p_fL,      g_fL);

    init_state_kernel<<<64, 512>>>(hidden, cell);
    embed_kernel<<<BATCH * TT, 128>>>(tgt, emb);

    // fp32 prep GEMMs
    gemm64_nn_f32<<<dim3(8, 32), 256>>>(enc, W_a, 512, p_encproj, 512);
    gemm64_nt_f32<<<dim3(32, 32), 256>>>(p_embF, W_ih0, 1024, p_embpre, 2048);
    gemm64_nt_f32<<<dim3(32, 32), 256>>>(enc, W_ih0 + 512, 1024, p_encIHC, 2048);

    // fused persistent recurrence (fp32, resident weights, overlapped splits)
    cudaFuncSetAttribute(decoder_persistent,
                         cudaFuncAttributeMaxDynamicSharedMemorySize, DSM_BYTES);
    decoder_persistent<<<NCTA, 256, DSM_BYTES>>>(enc, W_hh0, W_hh1, W_ih1,
                                                 b_ih0, b_hh0, b_ih1, b_hh1,
                                                 (const float4*)W_out);

    // tensor-core projection
    cudaFuncSetAttribute(big_gemm_mma, cudaFuncAttributeMaxDynamicSharedMemorySize, GEMM_SMEM);
    big_gemm_mma<<<dim3(16, VV / 128), 256, GEMM_SMEM>>>(p_fH, p_fL, p_WH, p_WL, b_out, out);

    tail_copy_kernel<<<64, 512>>>(out);
}

// round 14
// speedup vs baseline: 1.0665x; 1.0665x over previous
#include <cuda_runtime.h>
#include <cuda_bf16.h>
#include <math.h>
#include <stdint.h>

// Problem constants
#define BATCH 32
#define TT 64
#define SS 64
#define VV 32000
#define EE 512
#define HH 512
#define NCTA 128

// ---------------- device scratch ----------------
__device__ float g_embF[2048 * 512];             // embedded fp32, row = t*32+b
__device__ float g_encproj[2048 * 512];          // enc @ W_a, row = b*64+s
__device__ float g_encIHC[2048 * 2048];          // enc @ Wih0[:,512:]^T
__device__ float g_h[2 * BATCH * HH];            // fp32 state [h0 | h1(bufA)]
__device__ float g_h1B[BATCH * HH];              // h1 double buffer B
__device__ float g_c[2 * BATCH * HH];
__device__ float g_feat[TT * BATCH * 1024];      // [t][b][ h1 | ctx ]
__device__ float g_embpre[TT * BATCH * 2048];    // emb @ Wih0[:, :512]^T
__device__ float g_g0hh[BATCH * 2048];
__device__ float g_g0ctx[BATCH * 2048];
__device__ unsigned g_barcnt;
// bf16 split operands for big projection GEMM
__device__ __nv_bfloat16 g_WH[VV * 1024];
__device__ __nv_bfloat16 g_WL[VV * 1024];
__device__ __nv_bfloat16 g_fH[2048 * 1024];
__device__ __nv_bfloat16 g_fL[2048 * 1024];

// ---------------- PTX helpers ----------------
__device__ __forceinline__ uint32_t smem_to_u32(const void* p) {
    uint32_t a;
    asm("{ .reg .u64 t; cvta.to.shared.u64 t, %1; cvt.u32.u64 %0, t; }" : "=r"(a) : "l"(p));
    return a;
}
#define CP16(dst, src) \
    asm volatile("cp.async.cg.shared.global [%0], [%1], 16;" \
                 :: "r"(dst), "l"(src) : "memory")
#define CP_COMMIT() asm volatile("cp.async.commit_group;" ::: "memory")
#define CP_WAIT0()  asm volatile("cp.async.wait_group 0;" ::: "memory")
#define CP_WAIT1()  asm volatile("cp.async.wait_group 1;" ::: "memory")

#define LDSM_X4(r0, r1, r2, r3, addr) \
    asm volatile("ldmatrix.sync.aligned.m8n8.x4.shared.b16 {%0,%1,%2,%3}, [%4];" \
                 : "=r"(r0), "=r"(r1), "=r"(r2), "=r"(r3) : "r"(addr))
#define LDSM_X2(r0, r1, addr) \
    asm volatile("ldmatrix.sync.aligned.m8n8.x2.shared.b16 {%0,%1}, [%2];" \
                 : "=r"(r0), "=r"(r1) : "r"(addr))

#define MMA_BF16(c, a0, a1, a2, a3, b0, b1) \
    asm volatile("mma.sync.aligned.m16n8k16.row.col.f32.bf16.bf16.f32 " \
                 "{%0,%1,%2,%3}, {%4,%5,%6,%7}, {%8,%9}, {%0,%1,%2,%3};" \
                 : "+f"((c)[0]), "+f"((c)[1]), "+f"((c)[2]), "+f"((c)[3]) \
                 : "r"(a0), "r"(a1), "r"(a2), "r"(a3), "r"(b0), "r"(b1))

__device__ __forceinline__ unsigned short bf16hi(float x) {
    return __bfloat16_as_ushort(__float2bfloat16(x));
}
__device__ __forceinline__ void split4(float4 x, uint2& hv, uint2& lv) {
    unsigned short h0 = bf16hi(x.x), h1 = bf16hi(x.y), h2 = bf16hi(x.z), h3 = bf16hi(x.w);
    unsigned short l0 = bf16hi(x.x - __bfloat162float(__ushort_as_bfloat16(h0)));
    unsigned short l1 = bf16hi(x.y - __bfloat162float(__ushort_as_bfloat16(h1)));
    unsigned short l2 = bf16hi(x.z - __bfloat162float(__ushort_as_bfloat16(h2)));
    unsigned short l3 = bf16hi(x.w - __bfloat162float(__ushort_as_bfloat16(h3)));
    hv.x = (uint32_t)h0 | ((uint32_t)h1 << 16);
    hv.y = (uint32_t)h2 | ((uint32_t)h3 << 16);
    lv.x = (uint32_t)l0 | ((uint32_t)l1 << 16);
    lv.y = (uint32_t)l2 | ((uint32_t)l3 << 16);
}

// ---------------- utility kernels ----------------
__global__ void init_state_kernel(const float* __restrict__ hidden,
                                  const float* __restrict__ cell) {
    int i = blockIdx.x * blockDim.x + threadIdx.x;
    if (i == 0) g_barcnt = 0u;
    if (i < 2 * BATCH * HH) { g_h[i] = hidden[i]; g_c[i] = cell[i]; }
}

__global__ void tail_copy_kernel(float* __restrict__ out) {
    int i = blockIdx.x * blockDim.x + threadIdx.x;
    const long long OFF = (long long)BATCH * TT * VV;
    if (i < 2 * BATCH * HH) {
        out[OFF + i] = g_h[i];
        out[OFF + 2 * BATCH * HH + i] = g_c[i];
    }
}

__global__ void embed_kernel(const int* __restrict__ tgt,
                             const float* __restrict__ emb) {
    int blk = blockIdx.x;             // b*TT + t
    int b = blk >> 6, t = blk & 63;
    int idx = tgt[blk];
    int e = threadIdx.x * 4;
    float4 v;
    if (idx == 0) { v.x = v.y = v.z = v.w = 0.f; }
    else v = *reinterpret_cast<const float4*>(emb + (long long)idx * EE + e);
    *reinterpret_cast<float4*>(g_embF + (long long)(t * 32 + b) * 512 + e) = v;
}

// ---------------- fp32 prep GEMM (NT): C = A[:,512] @ B^T -------------------
__global__ __launch_bounds__(256)
void gemm64_nt_f32(const float* __restrict__ A,
                   const float* __restrict__ B, int ldb,
                   float* __restrict__ C, int ldc) {
    __shared__ __align__(16) float As[16][68];
    __shared__ __align__(16) float Bs[16][68];
    const int tid = threadIdx.x;
    const int m0 = blockIdx.y * 64, n0 = blockIdx.x * 64;
    const int lr = tid >> 2, lc = (tid & 3) * 4;
    const int tm = (tid >> 4) * 4, tn = (tid & 15) * 4;
    float acc[4][4] = {};
    for (int k0 = 0; k0 < 512; k0 += 16) {
        float4 av = *reinterpret_cast<const float4*>(A + (long long)(m0 + lr) * 512 + k0 + lc);
        As[lc + 0][lr] = av.x; As[lc + 1][lr] = av.y; As[lc + 2][lr] = av.z; As[lc + 3][lr] = av.w;
        float4 wv = *reinterpret_cast<const float4*>(B + (long long)(n0 + lr) * ldb + k0 + lc);
        Bs[lc + 0][lr] = wv.x; Bs[lc + 1][lr] = wv.y; Bs[lc + 2][lr] = wv.z; Bs[lc + 3][lr] = wv.w;
        __syncthreads();
        #pragma unroll
        for (int kk = 0; kk < 16; kk++) {
            float4 a = *reinterpret_cast<const float4*>(&As[kk][tm]);
            float4 b = *reinterpret_cast<const float4*>(&Bs[kk][tn]);
            acc[0][0] += a.x * b.x; acc[0][1] += a.x * b.y; acc[0][2] += a.x * b.z; acc[0][3] += a.x * b.w;
            acc[1][0] += a.y * b.x; acc[1][1] += a.y * b.y; acc[1][2] += a.y * b.z; acc[1][3] += a.y * b.w;
            acc[2][0] += a.z * b.x; acc[2][1] += a.z * b.y; acc[2][2] += a.z * b.z; acc[2][3] += a.z * b.w;
            acc[3][0] += a.w * b.x; acc[3][1] += a.w * b.y; acc[3][2] += a.w * b.z; acc[3][3] += a.w * b.w;
        }
        __syncthreads();
    }
    #pragma unroll
    for (int i = 0; i < 4; i++) {
        float4 o = make_float4(acc[i][0], acc[i][1], acc[i][2], acc[i][3]);
        *reinterpret_cast<float4*>(C + (long long)(m0 + tm + i) * ldc + n0 + tn) = o;
    }
}

// ---------------- fp32 prep GEMM (NN): C = A[:,512] @ B ---------------------
__global__ __launch_bounds__(256)
void gemm64_nn_f32(const float* __restrict__ A,
                   const float* __restrict__ B, int ldb,
                   float* __restrict__ C, int ldc) {
    __shared__ __align__(16) float As[16][68];
    __shared__ __align__(16) float Bs[16][68];
    const int tid = threadIdx.x;
    const int m0 = blockIdx.y * 64, n0 = blockIdx.x * 64;
    const int lr = tid >> 2, lc = (tid & 3) * 4;
    const int kr = tid >> 4, jc = (tid & 15) * 4;
    const int tm = (tid >> 4) * 4, tn = (tid & 15) * 4;
    float acc[4][4] = {};
    for (int k0 = 0; k0 < 512; k0 += 16) {
        float4 av = *reinterpret_cast<const float4*>(A + (long long)(m0 + lr) * 512 + k0 + lc);
        As[lc + 0][lr] = av.x; As[lc + 1][lr] = av.y; As[lc + 2][lr] = av.z; As[lc + 3][lr] = av.w;
        float4 bv = *reinterpret_cast<const float4*>(B + (long long)(k0 + kr) * ldb + n0 + jc);
        *reinterpret_cast<float4*>(&Bs[kr][jc]) = bv;
        __syncthreads();
        #pragma unroll
        for (int kk = 0; kk < 16; kk++) {
            float4 a = *reinterpret_cast<const float4*>(&As[kk][tm]);
            float4 b = *reinterpret_cast<const float4*>(&Bs[kk][tn]);
            acc[0][0] += a.x * b.x; acc[0][1] += a.x * b.y; acc[0][2] += a.x * b.z; acc[0][3] += a.x * b.w;
            acc[1][0] += a.y * b.x; acc[1][1] += a.y * b.y; acc[1][2] += a.y * b.z; acc[1][3] += a.y * b.w;
            acc[2][0] += a.z * b.x; acc[2][1] += a.z * b.y; acc[2][2] += a.z * b.z; acc[2][3] += a.z * b.w;
            acc[3][0] += a.w * b.x; acc[3][1] += a.w * b.y; acc[3][2] += a.w * b.z; acc[3][3] += a.w * b.w;
        }
        __syncthreads();
    }
    #pragma unroll
    for (int i = 0; i < 4; i++) {
        float4 o = make_float4(acc[i][0], acc[i][1], acc[i][2], acc[i][3]);
        *reinterpret_cast<float4*>(C + (long long)(m0 + tm + i) * ldc + n0 + tn) = o;
    }
}

// ---------------- persistent recurrence (fp32, 3 barriers/step) -------------
// smem: sA[512*33] (A k-major) | sB[32*512] | sC[32*17]
#define SA_FLOATS (512 * 33)
#define SB_FLOATS (32 * 512)
#define SC_FLOATS (32 * 17)
#define DSM_BYTES ((SA_FLOATS + SB_FLOATS + SC_FLOATS) * 4)

__device__ __forceinline__ float sigmf(float x) { return 1.f / (1.f + expf(-x)); }

// C[32 rows, 32 cols @ n0] = A[32x512] @ W[n0+j, :]^T   (fp32, full K=512)
__device__ __forceinline__ void fgemm_tile32(
    const float* __restrict__ A, const float* __restrict__ W, int sw, int n0,
    float* __restrict__ C, int ldc, float* sA, float* sB, int tid)
{
    const float* Wr = W + (long long)n0 * sw;
    for (int i = tid; i < 32 * 128; i += 256) {
        int col = i >> 7, kq = (i & 127) << 2;
        float4 v = __ldg(reinterpret_cast<const float4*>(Wr + (long long)col * sw + kq));
        *reinterpret_cast<float4*>(sB + col * 512 + kq) = v;
    }
    for (int i = tid; i < 32 * 128; i += 256) {
        int b = i >> 7, kq = (i & 127) << 2;
        float4 v = __ldcg(reinterpret_cast<const float4*>(A + b * 512 + kq));
        sA[(kq + 0) * 33 + b] = v.x;
        sA[(kq + 1) * 33 + b] = v.y;
        sA[(kq + 2) * 33 + b] = v.z;
        sA[(kq + 3) * 33 + b] = v.w;
    }
    __syncthreads();
    const int b = tid & 31, cg = tid >> 5;
    float a0c = 0.f, a1c = 0.f, a2c = 0.f, a3c = 0.f;
    const float* bp = sB + cg * 4 * 512;
    #pragma unroll 4
    for (int k = 0; k < 512; k += 4) {
        float a0 = sA[(k + 0) * 33 + b];
        float a1 = sA[(k + 1) * 33 + b];
        float a2 = sA[(k + 2) * 33 + b];
        float a3 = sA[(k + 3) * 33 + b];
        float4 b0 = *reinterpret_cast<const float4*>(bp + k);
        float4 b1 = *reinterpret_cast<const float4*>(bp + 512 + k);
        float4 b2 = *reinterpret_cast<const float4*>(bp + 1024 + k);
        float4 b3 = *reinterpret_cast<const float4*>(bp + 1536 + k);
        a0c += a0 * b0.x; a0c += a1 * b0.y; a0c += a2 * b0.z; a0c += a3 * b0.w;
        a1c += a0 * b1.x; a1c += a1 * b1.y; a1c += a2 * b1.z; a1c += a3 * b1.w;
        a2c += a0 * b2.x; a2c += a1 * b2.y; a2c += a2 * b2.z; a2c += a3 * b2.w;
        a3c += a0 * b3.x; a3c += a1 * b3.y; a3c += a2 * b3.z; a3c += a3 * b3.w;
    }
    __stcg(reinterpret_cast<float4*>(C + (long long)b * ldc + n0 + cg * 4),
           make_float4(a0c, a1c, a2c, a3c));
}

// 16-col accumulate gemm: cols are gate-interleaved j = cta*16 + c, with
// weight row n = (c&3)*512 + cta*4 + (c>>2). acc += A[32x512] @ W'^T.
__device__ __forceinline__ void gemm16_acc(
    const float* __restrict__ A, const float* __restrict__ W, int cta,
    float& a0c, float& a1c, float* sA, float* sB, int tid)
{
    __syncthreads();   // protect previous smem contents
    for (int i = tid; i < 16 * 128; i += 256) {
        int c = i >> 7, kq = (i & 127) << 2;
        int n = (c & 3) * 512 + cta * 4 + (c >> 2);
        float4 v = __ldg(reinterpret_cast<const float4*>(W + (long long)n * 512 + kq));
        *reinterpret_cast<float4*>(sB + c * 512 + kq) = v;
    }
    for (int i = tid; i < 32 * 128; i += 256) {
        int b = i >> 7, kq = (i & 127) << 2;
        float4 v = __ldcg(reinterpret_cast<const float4*>(A + b * 512 + kq));
        sA[(kq + 0) * 33 + b] = v.x;
        sA[(kq + 1) * 33 + b] = v.y;
        sA[(kq + 2) * 33 + b] = v.z;
        sA[(kq + 3) * 33 + b] = v.w;
    }
    __syncthreads();
    const int b = tid & 31, cg = tid >> 5;        // cg: 8 groups x 2 cols
    const float* bp = sB + cg * 2 * 512;
    #pragma unroll 4
    for (int k = 0; k < 512; k += 4) {
        float a0 = sA[(k + 0) * 33 + b];
        float a1 = sA[(k + 1) * 33 + b];
        float a2 = sA[(k + 2) * 33 + b];
        float a3 = sA[(k + 3) * 33 + b];
        float4 b0 = *reinterpret_cast<const float4*>(bp + k);
        float4 b1 = *reinterpret_cast<const float4*>(bp + 512 + k);
        a0c += a0 * b0.x; a0c += a1 * b0.y; a0c += a2 * b0.z; a0c += a3 * b0.w;
        a1c += a0 * b1.x; a1c += a1 * b1.y; a1c += a2 * b1.z; a1c += a3 * b1.w;
    }
}

__global__ __launch_bounds__(256, 1)
void decoder_persistent(const float* __restrict__ enc,
                        const float* __restrict__ W_hh0,
                        const float* __restrict__ W_hh1,
                        const float* __restrict__ W_ih1,
                        const float* __restrict__ b_ih0,
                        const float* __restrict__ b_hh0,
                        const float* __restrict__ b_ih1,
                        const float* __restrict__ b_hh1,
                        const float4* __restrict__ Wout4) {
    extern __shared__ float dsm[];
    float* sA = dsm;
    float* sB = dsm + SA_FLOATS;
    float* sC = dsm + SA_FLOATS + SB_FLOATS;
    // attn overlay (in sA region)
    float* h1s = sA;
    float* sc = sA + 512;
    float* sred = sA + 580;

    const int cta = blockIdx.x;
    const int tid = threadIdx.x;
    const int lane = tid & 31;
    const int wid = tid >> 5;
    unsigned bar_t = 0;
    unsigned* barp = &g_barcnt;

    auto gbar = [&]() {
        __syncthreads();
        bar_t += NCTA;
        if (tid == 0) {
            asm volatile("red.release.gpu.global.add.u32 [%0], 1;"
                         :: "l"(barp) : "memory");
            unsigned v;
            do {
                asm volatile("ld.acquire.gpu.global.u32 %0, [%1];"
                             : "=r"(v) : "l"(barp) : "memory");
            } while (v < bar_t);
        }
        __syncthreads();
    };

    float* h0 = g_h;
    float* h1A = g_h + 16384;
    float* h1B = g_h1B;

    for (int t = 0; t < TT; t++) {
        float* feat_t = g_feat + t * 32768;
        const float* ep = g_embpre + (long long)t * 65536;
        float* h1cur = (t & 1) ? h1B : h1A;
        float* h1nxt = (t & 1) ? h1A : h1B;

        // ==== Phase A: g0hh (0-63) | attn+ctx+g0ctx (64-95) | Wout split (96-127)
        if (cta < 64) {
            fgemm_tile32(h0, W_hh0, 512, cta * 32, g_g0hh, 2048, sA, sB, tid);
        } else if (cta < 96) {
            const int b = cta - 64;
            #pragma unroll
            for (int r = 0; r < 2; r++) {
                int k = tid + r * 256;
                h1s[k] = __ldcg(h1cur + b * 512 + k);
            }
            __syncthreads();
            const float* epj = g_encproj + (long long)b * 64 * 512;
            #pragma unroll
            for (int si = 0; si < 8; si++) {
                int s = wid * 8 + si;
                const float* row = epj + s * 512;
                float sum = 0.f;
                for (int j = lane; j < 512; j += 32) sum += row[j] * h1s[j];
                #pragma unroll
                for (int o = 16; o; o >>= 1) sum += __shfl_down_sync(0xffffffffu, sum, o);
                if (lane == 0) sc[s] = sum;
            }
            __syncthreads();
            if (tid == 0) {
                float mx = sc[0];
                for (int s = 1; s < 64; s++) mx = fmaxf(mx, sc[s]);
                sred[0] = mx;
            }
            __syncthreads();
            if (tid < 64) sc[tid] = expf(sc[tid] - sred[0]);
            __syncthreads();
            if (tid == 0) {
                float sm = 0.f;
                for (int s = 0; s < 64; s++) sm += sc[s];
                sred[1] = 1.f / sm;
            }
            __syncthreads();
            const float inv = sred[1];

            // ctx: 2 cols/thread
            {
                const float* encb = enc + (long long)b * SS * 512 + tid * 2;
                float c0 = 0.f, c1 = 0.f;
                #pragma unroll 8
                for (int s = 0; s < 64; s++) {
                    float w = sc[s];
                    float2 x = *reinterpret_cast<const float2*>(encb + s * 512);
                    c0 += w * x.x; c1 += w * x.y;
                }
                feat_t[b * 1024 + 512 + tid * 2]     = c0 * inv;
                feat_t[b * 1024 + 512 + tid * 2 + 1] = c1 * inv;
            }
            // g0ctx: 8 cols/thread from encIHC
            {
                const float* eb = g_encIHC + (long long)b * 64 * 2048 + tid * 8;
                float a8[8] = {0.f, 0.f, 0.f, 0.f, 0.f, 0.f, 0.f, 0.f};
                #pragma unroll 4
                for (int s = 0; s < 64; s++) {
                    float w = sc[s];
                    float4 x = *reinterpret_cast<const float4*>(eb + (long long)s * 2048);
                    float4 y = *reinterpret_cast<const float4*>(eb + (long long)s * 2048 + 4);
                    a8[0] += w * x.x; a8[1] += w * x.y; a8[2] += w * x.z; a8[3] += w * x.w;
                    a8[4] += w * y.x; a8[5] += w * y.y; a8[6] += w * y.z; a8[7] += w * y.w;
                }
                float* o = g_g0ctx + b * 2048 + tid * 8;
                #pragma unroll
                for (int j = 0; j < 8; j++) __stcg(o + j, a8[j] * inv);
            }
            __syncthreads();
        } else {
            // W_out split: 4000 float4 per CTA per step (32 CTAs x 4000 = 128000)
            long long base4 = (long long)t * 128000 + (cta - 96) * 4000;
            #pragma unroll
            for (int k = 0; k < 16; k++) {
                int off = k * 256 + tid;
                if (off < 4000) {
                    long long i4 = base4 + off;
                    float4 x = __ldg(Wout4 + i4);
                    uint2 hv, lv;
                    split4(x, hv, lv);
                    reinterpret_cast<uint2*>(g_WH)[i4] = hv;
                    reinterpret_cast<uint2*>(g_WL)[i4] = lv;
                }
            }
        }
        gbar();

        // ==== Phase C: LSTM0 (tid<128) + feat(t-1) split (tid 128-191) ====
        if (tid < 128) {
            int idx = cta * 128 + tid;
            int b = idx >> 9, u = idx & 511;
            int gg0 = b * 2048 + u;
            float gv[4];
            #pragma unroll
            for (int q = 0; q < 4; q++) {
                int o = gg0 + q * 512;
                gv[q] = ep[o] + __ldcg(g_g0hh + o) + __ldcg(g_g0ctx + o)
                      + __ldg(b_ih0 + q * 512 + u) + __ldg(b_hh0 + q * 512 + u);
            }
            float cv = g_c[idx];
            float cn = sigmf(gv[1]) * cv + sigmf(gv[0]) * tanhf(gv[2]);
            float hn = sigmf(gv[3]) * tanhf(cn);
            g_c[idx] = cn;
            __stcg(h0 + idx, hn);
        } else if (tid < 192 && t > 0) {
            int i4 = (t - 1) * 8192 + cta * 64 + (tid - 128);
            float4 x = __ldcg(reinterpret_cast<const float4*>(g_feat) + i4);
            uint2 hv, lv;
            split4(x, hv, lv);
            reinterpret_cast<uint2*>(g_fH)[i4] = hv;
            reinterpret_cast<uint2*>(g_fL)[i4] = lv;
        }
        gbar();

        // ==== Phase DE: fused g1 = h1@Whh1'^T + h0@Wih1'^T, then LSTM1 ====
        {
            float a0c = 0.f, a1c = 0.f;
            gemm16_acc(h1cur, W_hh1, cta, a0c, a1c, sA, sB, tid);
            gemm16_acc(h0,    W_ih1, cta, a0c, a1c, sA, sB, tid);
            const int b = tid & 31, cg = tid >> 5;
            __syncthreads();
            sC[b * 17 + cg * 2 + 0] = a0c;
            sC[b * 17 + cg * 2 + 1] = a1c;
            __syncthreads();
            if (tid < 128) {
                int b2 = tid >> 2, ul = tid & 3;
                int u = cta * 4 + ul;
                float gv[4];
                #pragma unroll
                for (int q = 0; q < 4; q++) {
                    gv[q] = sC[b2 * 17 + ul * 4 + q]
                          + __ldg(b_ih1 + q * 512 + u) + __ldg(b_hh1 + q * 512 + u);
                }
                int idx = b2 * 512 + u;
                float cv = g_c[16384 + idx];
                float cn = sigmf(gv[1]) * cv + sigmf(gv[0]) * tanhf(gv[2]);
                float hn = sigmf(gv[3]) * tanhf(cn);
                g_c[16384 + idx] = cn;
                __stcg(h1nxt + idx, hn);
                feat_t[b2 * 1024 + u] = hn;
            }
        }
        gbar();
    }

    // final feat slice (t = 63) split
    if (tid < 64) {
        int i4 = 63 * 8192 + cta * 64 + tid;
        float4 x = __ldcg(reinterpret_cast<const float4*>(g_feat) + i4);
        uint2 hv, lv;
        split4(x, hv, lv);
        reinterpret_cast<uint2*>(g_fH)[i4] = hv;
        reinterpret_cast<uint2*>(g_fL)[i4] = lv;
    }
}

// ---------------- big projection GEMM (3-term bf16, unchanged) ----------------
#define GK 1024
#define KC 32
#define NKC (GK / KC)
#define RST 40
#define BUF_BF16 (128 * RST)
#define STAGE_BF16 (4 * BUF_BF16)
#define GEMM_SMEM (2 * STAGE_BF16 * 2)

__global__ __launch_bounds__(256, 1)
void big_gemm_mma(const __nv_bfloat16* __restrict__ AH, const __nv_bfloat16* __restrict__ AL,
                  const __nv_bfloat16* __restrict__ BH, const __nv_bfloat16* __restrict__ BL,
                  const float* __restrict__ bias, float* __restrict__ out) {
    extern __shared__ __nv_bfloat16 sm[];
    const int tid = threadIdx.x;
    const int lane = tid & 31;
    const int wid = tid >> 5;
    const int wm = wid >> 1;
    const int wn = wid & 1;
    const int m0 = blockIdx.x * 128;
    const int n0 = blockIdx.y * 128;
    const uint32_t smem_base = smem_to_u32(sm);

    float acc[2][8][4];
    #pragma unroll
    for (int i = 0; i < 2; i++)
        #pragma unroll
        for (int j = 0; j < 8; j++)
            #pragma unroll
            for (int v = 0; v < 4; v++) acc[i][j][v] = 0.f;

    auto load_stage = [&](int st, int kc) {
        const uint32_t sb = smem_base + st * STAGE_BF16 * 2;
        const int k0 = kc * KC;
        #pragma unroll
        for (int r = 0; r < 2; r++) {
            int idx = tid + r * 256;
            int row = idx >> 2, c = idx & 3;
            uint32_t doff = (uint32_t)(row * RST + c * 8) * 2;
            long long aoff = (long long)(m0 + row) * GK + k0 + c * 8;
            long long boff = (long long)(n0 + row) * GK + k0 + c * 8;
            CP16(sb + doff,                AH + aoff);
            CP16(sb + BUF_BF16 * 2 + doff, AL + aoff);
            CP16(sb + BUF_BF16 * 4 + doff, BH + boff);
            CP16(sb + BUF_BF16 * 6 + doff, BL + boff);
        }
        CP_COMMIT();
    };

    load_stage(0, 0);

    for (int kc = 0; kc < NKC; kc++) {
        const int st = kc & 1;
        if (kc + 1 < NKC) { load_stage(st ^ 1, kc + 1); CP_WAIT1(); }
        else              { CP_WAIT0(); }
        __syncthreads();

        const uint32_t sb = smem_base + st * STAGE_BF16 * 2;
        uint32_t ah[2][2][4], al[2][2][4];
        #pragma unroll
        for (int i = 0; i < 2; i++)
            #pragma unroll
            for (int kk = 0; kk < 2; kk++) {
                uint32_t addr = sb + (uint32_t)((wm * 32 + i * 16 + (lane & 15)) * RST
                                                + kk * 16 + (lane >> 4) * 8) * 2;
                LDSM_X4(ah[i][kk][0], ah[i][kk][1], ah[i][kk][2], ah[i][kk][3], addr);
                LDSM_X4(al[i][kk][0], al[i][kk][1], al[i][kk][2], al[i][kk][3],
                        addr + BUF_BF16 * 2);
            }
        #pragma unroll
        for (int j = 0; j < 8; j++) {
            #pragma unroll
            for (int kk = 0; kk < 2; kk++) {
                uint32_t baddr = sb + BUF_BF16 * 4
                    + (uint32_t)((wn * 64 + j * 8 + (lane & 7)) * RST
                                 + kk * 16 + ((lane >> 3) & 1) * 8) * 2;
                uint32_t bh0, bh1, bl0, bl1;
                LDSM_X2(bh0, bh1, baddr);
                LDSM_X2(bl0, bl1, baddr + BUF_BF16 * 2);
                #pragma unroll
                for (int i = 0; i < 2; i++) {
                    MMA_BF16(acc[i][j], ah[i][kk][0], ah[i][kk][1], ah[i][kk][2], ah[i][kk][3], bh0, bh1);
                    MMA_BF16(acc[i][j], al[i][kk][0], al[i][kk][1], al[i][kk][2], al[i][kk][3], bh0, bh1);
                    MMA_BF16(acc[i][j], ah[i][kk][0], ah[i][kk][1], ah[i][kk][2], ah[i][kk][3], bl0, bl1);
                }
            }
        }
        __syncthreads();
    }

    #pragma unroll
    for (int i = 0; i < 2; i++) {
        int mA = m0 + wm * 32 + i * 16 + (lane >> 2);
        int mB = mA + 8;
        int tA = mA >> 5, bA = mA & 31;
        int tB = mB >> 5, bB = mB & 31;
        float* rowA = out + (long long)((bA << 6) + tA) * VV;
        float* rowB = out + (long long)((bB << 6) + tB) * VV;
        #pragma unroll
        for (int j = 0; j < 8; j++) {
            int n = n0 + wn * 64 + j * 8 + (lane & 3) * 2;
            float bv0 = bias[n], bv1 = bias[n + 1];
            float2 vA = make_float2(acc[i][j][0] + bv0, acc[i][j][1] + bv1);
            float2 vB = make_float2(acc[i][j][2] + bv0, acc[i][j][3] + bv1);
            *reinterpret_cast<float2*>(rowA + n) = vA;
            *reinterpret_cast<float2*>(rowB + n) = vB;
        }
    }
}

// ---------------- host launcher ----------------
extern "C" void kernel_launch(void* const* d_in, const int* in_sizes, int n_in,
                              void* d_out, int out_size) {
    const int*   tgt    = (const int*)  d_in[0];
    const float* enc    = (const float*)d_in[1];
    const float* hidden = (const float*)d_in[2];
    const float* cell   = (const float*)d_in[3];
    const float* emb    = (const float*)d_in[4];
    const float* W_a    = (const float*)d_in[5];
    const float* W_ih0  = (const float*)d_in[6];
    const float* W_hh0  = (const float*)d_in[7];
    const float* b_ih0  = (const float*)d_in[8];
    const float* b_hh0  = (const float*)d_in[9];
    const float* W_ih1  = (const float*)d_in[10];
    const float* W_hh1  = (const float*)d_in[11];
    const float* b_ih1  = (const float*)d_in[12];
    const float* b_hh1  = (const float*)d_in[13];
    const float* W_out  = (const float*)d_in[14];
    const float* b_out  = (const float*)d_in[15];
    float* out = (float*)d_out;

    float *p_embF, *p_encproj, *p_encIHC, *p_embpre;
    __nv_bfloat16 *p_WH, *p_WL, *p_fH, *p_fL;
    cudaGetSymbolAddress((void**)&p_embF,    g_embF);
    cudaGetSymbolAddress((void**)&p_encproj, g_encproj);
    cudaGetSymbolAddress((void**)&p_encIHC,  g_encIHC);
    cudaGetSymbolAddress((void**)&p_embpre,  g_embpre);
    cudaGetSymbolAddress((void**)&p_WH,      g_WH);
    cudaGetSymbolAddress((void**)&p_WL,      g_WL);
    cudaGetSymbolAddress((void**)&p_fH,      g_fH);
    cudaGetSymbolAddress((void**)&p_fL,      g_fL);

    init_state_kernel<<<64, 512>>>(hidden, cell);
    embed_kernel<<<BATCH * TT, 128>>>(tgt, emb);

    // fp32 prep GEMMs
    gemm64_nn_f32<<<dim3(8, 32), 256>>>(enc, W_a, 512, p_encproj, 512);
    gemm64_nt_f32<<<dim3(32, 32), 256>>>(p_embF, W_ih0, 1024, p_embpre, 2048);
    gemm64_nt_f32<<<dim3(32, 32), 256>>>(enc, W_ih0 + 512, 1024, p_encIHC, 2048);

    // fused persistent recurrence (fp32, 3 barriers/step, splits folded in)
    cudaFuncSetAttribute(decoder_persistent,
                         cudaFuncAttributeMaxDynamicSharedMemorySize, DSM_BYTES);
    decoder_persistent<<<NCTA, 256, DSM_BYTES>>>(enc, W_hh0, W_hh1, W_ih1,
                                                 b_ih0, b_hh0, b_ih1, b_hh1,
                                                 (const float4*)W_out);

    // tensor-core projection
    cudaFuncSetAttribute(big_gemm_mma, cudaFuncAttributeMaxDynamicSharedMemorySize, GEMM_SMEM);
    big_gemm_mma<<<dim3(16, VV / 128), 256, GEMM_SMEM>>>(p_fH, p_fL, p_WH, p_WL, b_out, out);

    tail_copy_kernel<<<64, 512>>>(out);
}

// round 15
// speedup vs baseline: 1.0751x; 1.0081x over previous
#include <cuda_runtime.h>
#include <cuda_bf16.h>
#include <math.h>
#include <stdint.h>

// Problem constants
#define BATCH 32
#define TT 64
#define SS 64
#define VV 32000
#define EE 512
#define HH 512
#define NCTA 128

// ---------------- device scratch ----------------
__device__ float g_embF[2048 * 512];             // embedded fp32, row = t*32+b
__device__ float g_encproj[2048 * 512];          // enc @ W_a, row = b*64+s
__device__ float g_encIHC[2048 * 2048];          // enc @ Wih0[:,512:]^T
__device__ float g_h[2 * BATCH * HH];            // fp32 state [h0 | h1(bufA)]
__device__ float g_h1B[BATCH * HH];              // h1 double buffer B
__device__ float g_c[2 * BATCH * HH];
__device__ float g_feat[TT * BATCH * 1024];      // [t][b][ h1 | ctx ]
__device__ float g_embpre[TT * BATCH * 2048];    // emb @ Wih0[:, :512]^T
__device__ float g_g0hh[BATCH * 2048];
__device__ float g_g0ctx[BATCH * 2048];
__device__ unsigned g_barcnt;
// bf16 split operands for big projection GEMM
__device__ __nv_bfloat16 g_WH[VV * 1024];
__device__ __nv_bfloat16 g_WL[VV * 1024];
__device__ __nv_bfloat16 g_fH[2048 * 1024];
__device__ __nv_bfloat16 g_fL[2048 * 1024];

// ---------------- PTX helpers ----------------
__device__ __forceinline__ uint32_t smem_to_u32(const void* p) {
    uint32_t a;
    asm("{ .reg .u64 t; cvta.to.shared.u64 t, %1; cvt.u32.u64 %0, t; }" : "=r"(a) : "l"(p));
    return a;
}
#define CP16(dst, src) \
    asm volatile("cp.async.cg.shared.global [%0], [%1], 16;" \
                 :: "r"(dst), "l"(src) : "memory")
#define CP_COMMIT() asm volatile("cp.async.commit_group;" ::: "memory")
#define CP_WAIT0()  asm volatile("cp.async.wait_group 0;" ::: "memory")
#define CP_WAIT1()  asm volatile("cp.async.wait_group 1;" ::: "memory")

#define LDSM_X4(r0, r1, r2, r3, addr) \
    asm volatile("ldmatrix.sync.aligned.m8n8.x4.shared.b16 {%0,%1,%2,%3}, [%4];" \
                 : "=r"(r0), "=r"(r1), "=r"(r2), "=r"(r3) : "r"(addr))
#define LDSM_X2(r0, r1, addr) \
    asm volatile("ldmatrix.sync.aligned.m8n8.x2.shared.b16 {%0,%1}, [%2];" \
                 : "=r"(r0), "=r"(r1) : "r"(addr))

#define MMA_BF16(c, a0, a1, a2, a3, b0, b1) \
    asm volatile("mma.sync.aligned.m16n8k16.row.col.f32.bf16.bf16.f32 " \
                 "{%0,%1,%2,%3}, {%4,%5,%6,%7}, {%8,%9}, {%0,%1,%2,%3};" \
                 : "+f"((c)[0]), "+f"((c)[1]), "+f"((c)[2]), "+f"((c)[3]) \
                 : "r"(a0), "r"(a1), "r"(a2), "r"(a3), "r"(b0), "r"(b1))

__device__ __forceinline__ unsigned short bf16hi(float x) {
    return __bfloat16_as_ushort(__float2bfloat16(x));
}
__device__ __forceinline__ void split4(float4 x, uint2& hv, uint2& lv) {
    unsigned short h0 = bf16hi(x.x), h1 = bf16hi(x.y), h2 = bf16hi(x.z), h3 = bf16hi(x.w);
    unsigned short l0 = bf16hi(x.x - __bfloat162float(__ushort_as_bfloat16(h0)));
    unsigned short l1 = bf16hi(x.y - __bfloat162float(__ushort_as_bfloat16(h1)));
    unsigned short l2 = bf16hi(x.z - __bfloat162float(__ushort_as_bfloat16(h2)));
    unsigned short l3 = bf16hi(x.w - __bfloat162float(__ushort_as_bfloat16(h3)));
    hv.x = (uint32_t)h0 | ((uint32_t)h1 << 16);
    hv.y = (uint32_t)h2 | ((uint32_t)h3 << 16);
    lv.x = (uint32_t)l0 | ((uint32_t)l1 << 16);
    lv.y = (uint32_t)l2 | ((uint32_t)l3 << 16);
}

// ---------------- utility kernels ----------------
__global__ void init_state_kernel(const float* __restrict__ hidden,
                                  const float* __restrict__ cell) {
    int i = blockIdx.x * blockDim.x + threadIdx.x;
    if (i == 0) g_barcnt = 0u;
    if (i < 2 * BATCH * HH) { g_h[i] = hidden[i]; g_c[i] = cell[i]; }
}

__global__ void tail_copy_kernel(float* __restrict__ out) {
    int i = blockIdx.x * blockDim.x + threadIdx.x;
    const long long OFF = (long long)BATCH * TT * VV;
    if (i < 2 * BATCH * HH) {
        out[OFF + i] = g_h[i];
        out[OFF + 2 * BATCH * HH + i] = g_c[i];
    }
}

__global__ void embed_kernel(const int* __restrict__ tgt,
                             const float* __restrict__ emb) {
    int blk = blockIdx.x;             // b*TT + t
    int b = blk >> 6, t = blk & 63;
    int idx = tgt[blk];
    int e = threadIdx.x * 4;
    float4 v;
    if (idx == 0) { v.x = v.y = v.z = v.w = 0.f; }
    else v = *reinterpret_cast<const float4*>(emb + (long long)idx * EE + e);
    *reinterpret_cast<float4*>(g_embF + (long long)(t * 32 + b) * 512 + e) = v;
}

// ---------------- fused prep GEMM: z = 0 encproj (NN), 1 embpre (NT), 2 encIHC (NT)
__global__ __launch_bounds__(256)
void prep_gemms(const float* __restrict__ enc,
                const float* __restrict__ W_a,
                const float* __restrict__ W_ih0) {
    __shared__ __align__(16) float As[16][68];
    __shared__ __align__(16) float Bs[16][68];
    const int z = blockIdx.z;
    if (z == 0 && blockIdx.x >= 8) return;

    const float* A; const float* B; float* C;
    int ldb, ldc; bool nt;
    if (z == 0)      { A = enc;    B = W_a;         C = g_encproj; ldb = 512;  ldc = 512;  nt = false; }
    else if (z == 1) { A = g_embF; B = W_ih0;       C = g_embpre;  ldb = 1024; ldc = 2048; nt = true; }
    else             { A = enc;    B = W_ih0 + 512; C = g_encIHC;  ldb = 1024; ldc = 2048; nt = true; }

    const int tid = threadIdx.x;
    const int m0 = blockIdx.y * 64, n0 = blockIdx.x * 64;
    const int lr = tid >> 2, lc = (tid & 3) * 4;
    const int kr = tid >> 4, jc = (tid & 15) * 4;
    const int tm = (tid >> 4) * 4, tn = (tid & 15) * 4;
    float acc[4][4] = {};
    for (int k0 = 0; k0 < 512; k0 += 16) {
        float4 av = *reinterpret_cast<const float4*>(A + (long long)(m0 + lr) * 512 + k0 + lc);
        As[lc + 0][lr] = av.x; As[lc + 1][lr] = av.y; As[lc + 2][lr] = av.z; As[lc + 3][lr] = av.w;
        if (nt) {
            float4 wv = *reinterpret_cast<const float4*>(B + (long long)(n0 + lr) * ldb + k0 + lc);
            Bs[lc + 0][lr] = wv.x; Bs[lc + 1][lr] = wv.y; Bs[lc + 2][lr] = wv.z; Bs[lc + 3][lr] = wv.w;
        } else {
            float4 bv = *reinterpret_cast<const float4*>(B + (long long)(k0 + kr) * ldb + n0 + jc);
            *reinterpret_cast<float4*>(&Bs[kr][jc]) = bv;
        }
        __syncthreads();
        #pragma unroll
        for (int kk = 0; kk < 16; kk++) {
            float4 a = *reinterpret_cast<const float4*>(&As[kk][tm]);
            float4 b = *reinterpret_cast<const float4*>(&Bs[kk][tn]);
            acc[0][0] += a.x * b.x; acc[0][1] += a.x * b.y; acc[0][2] += a.x * b.z; acc[0][3] += a.x * b.w;
            acc[1][0] += a.y * b.x; acc[1][1] += a.y * b.y; acc[1][2] += a.y * b.z; acc[1][3] += a.y * b.w;
            acc[2][0] += a.z * b.x; acc[2][1] += a.z * b.y; acc[2][2] += a.z * b.z; acc[2][3] += a.z * b.w;
            acc[3][0] += a.w * b.x; acc[3][1] += a.w * b.y; acc[3][2] += a.w * b.z; acc[3][3] += a.w * b.w;
        }
        __syncthreads();
    }
    #pragma unroll
    for (int i = 0; i < 4; i++) {
        float4 o = make_float4(acc[i][0], acc[i][1], acc[i][2], acc[i][3]);
        *reinterpret_cast<float4*>(C + (long long)(m0 + tm + i) * ldc + n0 + tn) = o;
    }
}

// ---------------- persistent recurrence (fp32, 3 barriers/step) -------------
// smem: sA[1024*33] | sB[16*1024] | sC[32*17]  (phase A uses first 512 k-rows)
#define SA_FLOATS (1024 * 33)
#define SB_FLOATS (16 * 1024)
#define SC_FLOATS (32 * 17)
#define DSM_BYTES ((SA_FLOATS + SB_FLOATS + SC_FLOATS) * 4)

__device__ __forceinline__ float sigmf(float x) { return 1.f / (1.f + expf(-x)); }

// C[32 rows, 32 cols @ n0] = A[32x512] @ W[n0+j, :]^T   (fp32, full K=512)
// sB region must hold 32*512 floats (16*1024 = same size).
__device__ __forceinline__ void fgemm_tile32(
    const float* __restrict__ A, const float* __restrict__ W, int sw, int n0,
    float* __restrict__ C, int ldc, float* sA, float* sB, int tid)
{
    const float* Wr = W + (long long)n0 * sw;
    for (int i = tid; i < 32 * 128; i += 256) {
        int col = i >> 7, kq = (i & 127) << 2;
        float4 v = __ldg(reinterpret_cast<const float4*>(Wr + (long long)col * sw + kq));
        *reinterpret_cast<float4*>(sB + col * 512 + kq) = v;
    }
    for (int i = tid; i < 32 * 128; i += 256) {
        int b = i >> 7, kq = (i & 127) << 2;
        float4 v = __ldcg(reinterpret_cast<const float4*>(A + b * 512 + kq));
        sA[(kq + 0) * 33 + b] = v.x;
        sA[(kq + 1) * 33 + b] = v.y;
        sA[(kq + 2) * 33 + b] = v.z;
        sA[(kq + 3) * 33 + b] = v.w;
    }
    __syncthreads();
    const int b = tid & 31, cg = tid >> 5;
    float a0c = 0.f, a1c = 0.f, a2c = 0.f, a3c = 0.f;
    const float* bp = sB + cg * 4 * 512;
    #pragma unroll 4
    for (int k = 0; k < 512; k += 4) {
        float a0 = sA[(k + 0) * 33 + b];
        float a1 = sA[(k + 1) * 33 + b];
        float a2 = sA[(k + 2) * 33 + b];
        float a3 = sA[(k + 3) * 33 + b];
        float4 b0 = *reinterpret_cast<const float4*>(bp + k);
        float4 b1 = *reinterpret_cast<const float4*>(bp + 512 + k);
        float4 b2 = *reinterpret_cast<const float4*>(bp + 1024 + k);
        float4 b3 = *reinterpret_cast<const float4*>(bp + 1536 + k);
        a0c += a0 * b0.x; a0c += a1 * b0.y; a0c += a2 * b0.z; a0c += a3 * b0.w;
        a1c += a0 * b1.x; a1c += a1 * b1.y; a1c += a2 * b1.z; a1c += a3 * b1.w;
        a2c += a0 * b2.x; a2c += a1 * b2.y; a2c += a2 * b2.z; a2c += a3 * b2.w;
        a3c += a0 * b3.x; a3c += a1 * b3.y; a3c += a2 * b3.z; a3c += a3 * b3.w;
    }
    __stcg(reinterpret_cast<float4*>(C + (long long)b * ldc + n0 + cg * 4),
           make_float4(a0c, a1c, a2c, a3c));
}

__global__ __launch_bounds__(256, 1)
void decoder_persistent(const float* __restrict__ enc,
                        const float* __restrict__ W_hh0,
                        const float* __restrict__ W_hh1,
                        const float* __restrict__ W_ih1,
                        const float* __restrict__ b_ih0,
                        const float* __restrict__ b_hh0,
                        const float* __restrict__ b_ih1,
                        const float* __restrict__ b_hh1,
                        const float4* __restrict__ Wout4) {
    extern __shared__ float dsm[];
    float* sA = dsm;
    float* sB = dsm + SA_FLOATS;
    float* sC = dsm + SA_FLOATS + SB_FLOATS;
    // attn overlay (in sA region)
    float* h1s = sA;
    float* sc = sA + 512;
    float* sred = sA + 580;

    const int cta = blockIdx.x;
    const int tid = threadIdx.x;
    const int lane = tid & 31;
    const int wid = tid >> 5;
    unsigned bar_t = 0;
    unsigned* barp = &g_barcnt;

    auto gbar = [&]() {
        __syncthreads();
        bar_t += NCTA;
        if (tid == 0) {
            asm volatile("red.release.gpu.global.add.u32 [%0], 1;"
                         :: "l"(barp) : "memory");
            unsigned v;
            do {
                asm volatile("ld.acquire.gpu.global.u32 %0, [%1];"
                             : "=r"(v) : "l"(barp) : "memory");
            } while (v < bar_t);
        }
        __syncthreads();
    };

    float* h0 = g_h;
    float* h1A = g_h + 16384;
    float* h1B = g_h1B;

    for (int t = 0; t < TT; t++) {
        float* feat_t = g_feat + t * 32768;
        const float* ep = g_embpre + (long long)t * 65536;
        float* h1cur = (t & 1) ? h1B : h1A;
        float* h1nxt = (t & 1) ? h1A : h1B;

        // ==== Phase A: g0hh (0-63) | attn+ctx+g0ctx (64-95) | Wout split (96-127)
        if (cta < 64) {
            fgemm_tile32(h0, W_hh0, 512, cta * 32, g_g0hh, 2048, sA, sB, tid);
        } else if (cta < 96) {
            const int b = cta - 64;
            #pragma unroll
            for (int r = 0; r < 2; r++) {
                int k = tid + r * 256;
                h1s[k] = __ldcg(h1cur + b * 512 + k);
            }
            __syncthreads();
            const float* epj = g_encproj + (long long)b * 64 * 512;
            #pragma unroll
            for (int si = 0; si < 8; si++) {
                int s = wid * 8 + si;
                const float* row = epj + s * 512;
                float sum = 0.f;
                for (int j = lane; j < 512; j += 32) sum += row[j] * h1s[j];
                #pragma unroll
                for (int o = 16; o; o >>= 1) sum += __shfl_down_sync(0xffffffffu, sum, o);
                if (lane == 0) sc[s] = sum;
            }
            __syncthreads();
            if (tid == 0) {
                float mx = sc[0];
                for (int s = 1; s < 64; s++) mx = fmaxf(mx, sc[s]);
                sred[0] = mx;
            }
            __syncthreads();
            if (tid < 64) sc[tid] = expf(sc[tid] - sred[0]);
            __syncthreads();
            if (tid == 0) {
                float sm = 0.f;
                for (int s = 0; s < 64; s++) sm += sc[s];
                sred[1] = 1.f / sm;
            }
            __syncthreads();
            const float inv = sred[1];

            // ctx: 2 cols/thread
            {
                const float* encb = enc + (long long)b * SS * 512 + tid * 2;
                float c0 = 0.f, c1 = 0.f;
                #pragma unroll 8
                for (int s = 0; s < 64; s++) {
                    float w = sc[s];
                    float2 x = *reinterpret_cast<const float2*>(encb + s * 512);
                    c0 += w * x.x; c1 += w * x.y;
                }
                feat_t[b * 1024 + 512 + tid * 2]     = c0 * inv;
                feat_t[b * 1024 + 512 + tid * 2 + 1] = c1 * inv;
            }
            // g0ctx: 8 cols/thread from encIHC
            {
                const float* eb = g_encIHC + (long long)b * 64 * 2048 + tid * 8;
                float a8[8] = {0.f, 0.f, 0.f, 0.f, 0.f, 0.f, 0.f, 0.f};
                #pragma unroll 4
                for (int s = 0; s < 64; s++) {
                    float w = sc[s];
                    float4 x = *reinterpret_cast<const float4*>(eb + (long long)s * 2048);
                    float4 y = *reinterpret_cast<const float4*>(eb + (long long)s * 2048 + 4);
                    a8[0] += w * x.x; a8[1] += w * x.y; a8[2] += w * x.z; a8[3] += w * x.w;
                    a8[4] += w * y.x; a8[5] += w * y.y; a8[6] += w * y.z; a8[7] += w * y.w;
                }
                float* o = g_g0ctx + b * 2048 + tid * 8;
                #pragma unroll
                for (int j = 0; j < 8; j++) __stcg(o + j, a8[j] * inv);
            }
            __syncthreads();
        } else {
            // W_out split: 4000 float4 per CTA per step
            long long base4 = (long long)t * 128000 + (cta - 96) * 4000;
            #pragma unroll
            for (int k = 0; k < 16; k++) {
                int off = k * 256 + tid;
                if (off < 4000) {
                    long long i4 = base4 + off;
                    float4 x = __ldg(Wout4 + i4);
                    uint2 hv, lv;
                    split4(x, hv, lv);
                    reinterpret_cast<uint2*>(g_WH)[i4] = hv;
                    reinterpret_cast<uint2*>(g_WL)[i4] = lv;
                }
            }
        }
        gbar();

        // ==== Phase C: LSTM0 (tid<128) + feat(t-1) split (tid 128-191) ====
        if (tid < 128) {
            int idx = cta * 128 + tid;
            int b = idx >> 9, u = idx & 511;
            int gg0 = b * 2048 + u;
            float gv[4];
            #pragma unroll
            for (int q = 0; q < 4; q++) {
                int o = gg0 + q * 512;
                gv[q] = ep[o] + __ldcg(g_g0hh + o) + __ldcg(g_g0ctx + o)
                      + __ldg(b_ih0 + q * 512 + u) + __ldg(b_hh0 + q * 512 + u);
            }
            float cv = g_c[idx];
            float cn = sigmf(gv[1]) * cv + sigmf(gv[0]) * tanhf(gv[2]);
            float hn = sigmf(gv[3]) * tanhf(cn);
            g_c[idx] = cn;
            __stcg(h0 + idx, hn);
        } else if (tid < 192 && t > 0) {
            int i4 = (t - 1) * 8192 + cta * 64 + (tid - 128);
            float4 x = __ldcg(reinterpret_cast<const float4*>(g_feat) + i4);
            uint2 hv, lv;
            split4(x, hv, lv);
            reinterpret_cast<uint2*>(g_fH)[i4] = hv;
            reinterpret_cast<uint2*>(g_fL)[i4] = lv;
        }
        gbar();

        // ==== Phase DE: single-pass g1 = [h1|h0] @ [Whh1|Wih1]'^T, then LSTM1
        {
            // load 16 gate-interleaved weight cols over concat K=1024
            for (int i = tid; i < 16 * 256; i += 256) {
                int c = i >> 4, kq = (i & 15) << 2;          // c 0..15, kq 0..60? no:
                // redo mapping: 16 cols x 1024 k / 4 = 4096 float4; 16 iters/thread
                (void)c; (void)kq;
                break;
            }
            for (int it = 0; it < 16; it++) {
                int i = it * 256 + tid;                       // 0..4095
                int c = i >> 8, kq = (i & 255) << 2;          // c 0..15, kq 0..1020
                int n = (c & 3) * 512 + cta * 4 + (c >> 2);
                const float* src = (kq < 512)
                    ? (W_hh1 + (long long)n * 512 + kq)
                    : (W_ih1 + (long long)n * 512 + (kq - 512));
                float4 v = __ldg(reinterpret_cast<const float4*>(src));
                *reinterpret_cast<float4*>(sB + c * 1024 + kq) = v;
            }
            // load concat A: k 0-511 = h1cur, 512-1023 = h0
            for (int it = 0; it < 32; it++) {
                int i = it * 256 + tid;                       // 0..8191
                int b = i >> 8, kq = (i & 255) << 2;          // b 0..31, kq 0..1020
                const float* src = (kq < 512)
                    ? (h1cur + b * 512 + kq)
                    : (h0 + b * 512 + (kq - 512));
                float4 v = __ldcg(reinterpret_cast<const float4*>(src));
                sA[(kq + 0) * 33 + b] = v.x;
                sA[(kq + 1) * 33 + b] = v.y;
                sA[(kq + 2) * 33 + b] = v.z;
                sA[(kq + 3) * 33 + b] = v.w;
            }
            __syncthreads();
            const int b = tid & 31, cg = tid >> 5;
            float a0c = 0.f, a1c = 0.f;
            const float* bp = sB + cg * 2 * 1024;
            #pragma unroll 4
            for (int k = 0; k < 1024; k += 4) {
                float a0 = sA[(k + 0) * 33 + b];
                float a1 = sA[(k + 1) * 33 + b];
                float a2 = sA[(k + 2) * 33 + b];
                float a3 = sA[(k + 3) * 33 + b];
                float4 b0 = *reinterpret_cast<const float4*>(bp + k);
                float4 b1 = *reinterpret_cast<const float4*>(bp + 1024 + k);
                a0c += a0 * b0.x; a0c += a1 * b0.y; a0c += a2 * b0.z; a0c += a3 * b0.w;
                a1c += a0 * b1.x; a1c += a1 * b1.y; a1c += a2 * b1.z; a1c += a3 * b1.w;
            }
            __syncthreads();
            sC[b * 17 + cg * 2 + 0] = a0c;
            sC[b * 17 + cg * 2 + 1] = a1c;
            __syncthreads();
            if (tid < 128) {
                int b2 = tid >> 2, ul = tid & 3;
                int u = cta * 4 + ul;
                float gv[4];
                #pragma unroll
                for (int q = 0; q < 4; q++) {
                    gv[q] = sC[b2 * 17 + ul * 4 + q]
                          + __ldg(b_ih1 + q * 512 + u) + __ldg(b_hh1 + q * 512 + u);
                }
                int idx = b2 * 512 + u;
                float cv = g_c[16384 + idx];
                float cn = sigmf(gv[1]) * cv + sigmf(gv[0]) * tanhf(gv[2]);
                float hn = sigmf(gv[3]) * tanhf(cn);
                g_c[16384 + idx] = cn;
                __stcg(h1nxt + idx, hn);
                feat_t[b2 * 1024 + u] = hn;
            }
        }
        gbar();
    }

    // final feat slice (t = 63) split
    if (tid < 64) {
        int i4 = 63 * 8192 + cta * 64 + tid;
        float4 x = __ldcg(reinterpret_cast<const float4*>(g_feat) + i4);
        uint2 hv, lv;
        split4(x, hv, lv);
        reinterpret_cast<uint2*>(g_fH)[i4] = hv;
        reinterpret_cast<uint2*>(g_fL)[i4] = lv;
    }
}

// ---------------- big projection GEMM (3-term bf16, unchanged) ----------------
#define GK 1024
#define KC 32
#define NKC (GK / KC)
#define RST 40
#define BUF_BF16 (128 * RST)
#define STAGE_BF16 (4 * BUF_BF16)
#define GEMM_SMEM (2 * STAGE_BF16 * 2)

__global__ __launch_bounds__(256, 1)
void big_gemm_mma(const __nv_bfloat16* __restrict__ AH, const __nv_bfloat16* __restrict__ AL,
                  const __nv_bfloat16* __restrict__ BH, const __nv_bfloat16* __restrict__ BL,
                  const float* __restrict__ bias, float* __restrict__ out) {
    extern __shared__ __nv_bfloat16 sm[];
    const int tid = threadIdx.x;
    const int lane = tid & 31;
    const int wid = tid >> 5;
    const int wm = wid >> 1;
    const int wn = wid & 1;
    const int m0 = blockIdx.x * 128;
    const int n0 = blockIdx.y * 128;
    const uint32_t smem_base = smem_to_u32(sm);

    float acc[2][8][4];
    #pragma unroll
    for (int i = 0; i < 2; i++)
        #pragma unroll
        for (int j = 0; j < 8; j++)
            #pragma unroll
            for (int v = 0; v < 4; v++) acc[i][j][v] = 0.f;

    auto load_stage = [&](int st, int kc) {
        const uint32_t sb = smem_base + st * STAGE_BF16 * 2;
        const int k0 = kc * KC;
        #pragma unroll
        for (int r = 0; r < 2; r++) {
            int idx = tid + r * 256;
            int row = idx >> 2, c = idx & 3;
            uint32_t doff = (uint32_t)(row * RST + c * 8) * 2;
            long long aoff = (long long)(m0 + row) * GK + k0 + c * 8;
            long long boff = (long long)(n0 + row) * GK + k0 + c * 8;
            CP16(sb + doff,                AH + aoff);
            CP16(sb + BUF_BF16 * 2 + doff, AL + aoff);
            CP16(sb + BUF_BF16 * 4 + doff, BH + boff);
            CP16(sb + BUF_BF16 * 6 + doff, BL + boff);
        }
        CP_COMMIT();
    };

    load_stage(0, 0);

    for (int kc = 0; kc < NKC; kc++) {
        const int st = kc & 1;
        if (kc + 1 < NKC) { load_stage(st ^ 1, kc + 1); CP_WAIT1(); }
        else              { CP_WAIT0(); }
        __syncthreads();

        const uint32_t sb = smem_base + st * STAGE_BF16 * 2;
        uint32_t ah[2][2][4], al[2][2][4];
        #pragma unroll
        for (int i = 0; i < 2; i++)
            #pragma unroll
            for (int kk = 0; kk < 2; kk++) {
                uint32_t addr = sb + (uint32_t)((wm * 32 + i * 16 + (lane & 15)) * RST
                                                + kk * 16 + (lane >> 4) * 8) * 2;
                LDSM_X4(ah[i][kk][0], ah[i][kk][1], ah[i][kk][2], ah[i][kk][3], addr);
                LDSM_X4(al[i][kk][0], al[i][kk][1], al[i][kk][2], al[i][kk][3],
                        addr + BUF_BF16 * 2);
            }
        #pragma unroll
        for (int j = 0; j < 8; j++) {
            #pragma unroll
            for (int kk = 0; kk < 2; kk++) {
                uint32_t baddr = sb + BUF_BF16 * 4
                    + (uint32_t)((wn * 64 + j * 8 + (lane & 7)) * RST
                                 + kk * 16 + ((lane >> 3) & 1) * 8) * 2;
                uint32_t bh0, bh1, bl0, bl1;
                LDSM_X2(bh0, bh1, baddr);
                LDSM_X2(bl0, bl1, baddr + BUF_BF16 * 2);
                #pragma unroll
                for (int i = 0; i < 2; i++) {
                    MMA_BF16(acc[i][j], ah[i][kk][0], ah[i][kk][1], ah[i][kk][2], ah[i][kk][3], bh0, bh1);
                    MMA_BF16(acc[i][j], al[i][kk][0], al[i][kk][1], al[i][kk][2], al[i][kk][3], bh0, bh1);
                    MMA_BF16(acc[i][j], ah[i][kk][0], ah[i][kk][1], ah[i][kk][2], ah[i][kk][3], bl0, bl1);
                }
            }
        }
        __syncthreads();
    }

    #pragma unroll
    for (int i = 0; i < 2; i++) {
        int mA = m0 + wm * 32 + i * 16 + (lane >> 2);
        int mB = mA + 8;
        int tA = mA >> 5, bA = mA & 31;
        int tB = mB >> 5, bB = mB & 31;
        float* rowA = out + (long long)((bA << 6) + tA) * VV;
        float* rowB = out + (long long)((bB << 6) + tB) * VV;
        #pragma unroll
        for (int j = 0; j < 8; j++) {
            int n = n0 + wn * 64 + j * 8 + (lane & 3) * 2;
            float bv0 = bias[n], bv1 = bias[n + 1];
            float2 vA = make_float2(acc[i][j][0] + bv0, acc[i][j][1] + bv1);
            float2 vB = make_float2(acc[i][j][2] + bv0, acc[i][j][3] + bv1);
            *reinterpret_cast<float2*>(rowA + n) = vA;
            *reinterpret_cast<float2*>(rowB + n) = vB;
        }
    }
}

// ---------------- host launcher ----------------
extern "C" void kernel_launch(void* const* d_in, const int* in_sizes, int n_in,
                              void* d_out, int out_size) {
    const int*   tgt    = (const int*)  d_in[0];
    const float* enc    = (const float*)d_in[1];
    const float* hidden = (const float*)d_in[2];
    const float* cell   = (const float*)d_in[3];
    const float* emb    = (const float*)d_in[4];
    const float* W_a    = (const float*)d_in[5];
    const float* W_ih0  = (const float*)d_in[6];
    const float* W_hh0  = (const float*)d_in[7];
    const float* b_ih0  = (const float*)d_in[8];
    const float* b_hh0  = (const float*)d_in[9];
    const float* W_ih1  = (const float*)d_in[10];
    const float* W_hh1  = (const float*)d_in[11];
    const float* b_ih1  = (const float*)d_in[12];
    const float* b_hh1  = (const float*)d_in[13];
    const float* W_out  = (const float*)d_in[14];
    const float* b_out  = (const float*)d_in[15];
    float* out = (float*)d_out;

    __nv_bfloat16 *p_WH, *p_WL, *p_fH, *p_fL;
    cudaGetSymbolAddress((void**)&p_WH, g_WH);
    cudaGetSymbolAddress((void**)&p_WL, g_WL);
    cudaGetSymbolAddress((void**)&p_fH, g_fH);
    cudaGetSymbolAddress((void**)&p_fL, g_fL);

    init_state_kernel<<<64, 512>>>(hidden, cell);
    embed_kernel<<<BATCH * TT, 128>>>(tgt, emb);

    // fused fp32 prep GEMMs (encproj | embpre | encIHC concurrently)
    prep_gemms<<<dim3(32, 32, 3), 256>>>(enc, W_a, W_ih0);

    // fused persistent recurrence (fp32, 3 barriers/step, splits folded in)
    cudaFuncSetAttribute(decoder_persistent,
                         cudaFuncAttributeMaxDynamicSharedMemorySize, DSM_BYTES);
    decoder_persistent<<<NCTA, 256, DSM_BYTES>>>(enc, W_hh0, W_hh1, W_ih1,
                                                 b_ih0, b_hh0, b_ih1, b_hh1,
                                                 (const float4*)W_out);

    // tensor-core projection
    cudaFuncSetAttribute(big_gemm_mma, cudaFuncAttributeMaxDynamicSharedMemorySize, GEMM_SMEM);
    big_gemm_mma<<<dim3(16, VV / 128), 256, GEMM_SMEM>>>(p_fH, p_fL, p_WH, p_WL, b_out, out);

    tail_copy_kernel<<<64, 512>>>(out);
}